// round 6
// baseline (speedup 1.0000x reference)
#include <cuda_runtime.h>

using u64 = unsigned long long;
#define FULL_MASK 0xFFFFFFFFu

constexpr int IN_DIM  = 256;
constexpr int D       = 32;
constexpr int RPT     = 8;            // rows per tile (= warps per block)
constexpr int NRF     = RPT * 3;      // 24 (row,feat) units per tile
constexpr int THREADS = 256;          // 8 warps
constexpr int WSTRIDE = 36;           // small-mat row stride
constexpr float LN_EPS = 1e-5f;

struct Smem {
    float f[NRF * IN_DIM];            // 24576 B staged input rows
    float part[NRF * D * 2];          // 6144 B  [rf][j][kg]
    float x[NRF * D];                 // 3072 B  LN outputs
    float w5[5 * D * WSTRIDE];        // 23040 B Wq,Wk,Wv,Wo1,Wo2
    float pooled[RPT][D];             // 1024 B
    float o1[RPT][D];                 // 1024 B
};                                    // ~57.5 KB -> 3 blocks/SM (reg-limited)

__device__ __forceinline__ void ffma2(u64& d, u64 a, u64 b) {
    asm("fma.rn.f32x2 %0, %1, %2, %0;" : "+l"(d) : "l"(a), "l"(b));
}
__device__ __forceinline__ float hsum2(u64 a, u64 b) {
    return __uint_as_float((unsigned)a) + __uint_as_float((unsigned)(a >> 32))
         + __uint_as_float((unsigned)b) + __uint_as_float((unsigned)(b >> 32));
}
__device__ __forceinline__ float wsum(float v) {
    v += __shfl_xor_sync(FULL_MASK, v, 16);
    v += __shfl_xor_sync(FULL_MASK, v, 8);
    v += __shfl_xor_sync(FULL_MASK, v, 4);
    v += __shfl_xor_sync(FULL_MASK, v, 2);
    v += __shfl_xor_sync(FULL_MASK, v, 1);
    return v;
}
__device__ __forceinline__ void cp16(void* smem_dst, const void* gsrc) {
    unsigned d = (unsigned)__cvta_generic_to_shared(smem_dst);
    asm volatile("cp.async.cg.shared.global [%0], [%1], 16;" :: "r"(d), "l"(gsrc));
}

__global__ __launch_bounds__(THREADS, 3)
void msfe_kernel(const float* __restrict__ f1, const float* __restrict__ f4,
                 const float* __restrict__ fD,
                 const float* __restrict__ Wp,  const float* __restrict__ bp,
                 const float* __restrict__ ln_g, const float* __restrict__ ln_b,
                 const float* __restrict__ Wq,  const float* __restrict__ bq,
                 const float* __restrict__ Wk,  const float* __restrict__ bk,
                 const float* __restrict__ Wv,  const float* __restrict__ bv,
                 const float* __restrict__ Wo1, const float* __restrict__ bo1,
                 const float* __restrict__ Wo2, const float* __restrict__ bo2,
                 float* __restrict__ out, int B, int ntiles)
{
    extern __shared__ char smem_raw[];
    Smem* s = reinterpret_cast<Smem*>(smem_raw);

    const int tid  = threadIdx.x;
    const int lane = tid & 31;
    const int w    = tid >> 5;

    // warp role for projection: j-group (4) x k-half (2)
    const int jg   = w & 3;
    const int kg   = w >> 2;
    const int jl   = lane & 7;
    const int ksub = lane >> 3;
    const int j    = 8 * jg + jl;      // this thread's Wp output row

    // ---- register-resident Wp slice: 32 floats, interleaved float4s ----
    // thread owns float4 indices (kg*32 + 4c + ksub), c = 0..7, of row j
    u64 wpp[16];
    {
        const u64* src = reinterpret_cast<const u64*>(Wp + j * IN_DIM);
        #pragma unroll
        for (int c = 0; c < 8; c++) {
            int f4i = kg * 32 + 4 * c + ksub;
            wpp[2 * c]     = src[2 * f4i];
            wpp[2 * c + 1] = src[2 * f4i + 1];
        }
    }

    // ---- stage small mats into smem ----
    for (int i = tid; i < D * D; i += THREADS) {
        int jj = i >> 5, dd = i & 31;
        int o = jj * WSTRIDE + dd;
        s->w5[0 * D * WSTRIDE + o] = Wq [i];
        s->w5[1 * D * WSTRIDE + o] = Wk [i];
        s->w5[2 * D * WSTRIDE + o] = Wv [i];
        s->w5[3 * D * WSTRIDE + o] = Wo1[i];
        s->w5[4 * D * WSTRIDE + o] = Wo2[i];
    }

    const float bp_t  = bp [j];        // bias for this thread's proj row
    const float bp_l  = bp [lane];     // per-lane (LN phase uses lane=j)
    const float g_l   = ln_g[lane];
    const float b_l   = ln_b[lane];
    const float bq_l  = bq [lane];
    const float bk_l  = bk [lane];
    const float bv_l  = bv [lane];
    const float bo1_l = bo1[lane];
    const float bo2_l = bo2[lane];
    (void)bp_t;

    // ---- f staging decomposition (6 x 16B per thread) ----
    // slot i = tid + k2*256 : rf = i>>6, c4 = i&63 ; rf = 3*r + ft
    auto issue_prefetch = [&](int row0) {
        float4* fdst = reinterpret_cast<float4*>(s->f);
        #pragma unroll
        for (int k2 = 0; k2 < 6; k2++) {
            int i  = tid + k2 * THREADS;
            int rf = i >> 6;
            int c4 = i & 63;
            int r  = rf / 3;
            int ft = rf - 3 * r;
            int row = row0 + r;
            const float* src = (ft == 0) ? f1 : (ft == 1) ? f4 : fD;
            if (row < B) {
                cp16(&fdst[i], src + (size_t)row * IN_DIM + c4 * 4);
            } else {
                fdst[i] = make_float4(0.f, 0.f, 0.f, 0.f);
            }
        }
        asm volatile("cp.async.commit_group;" ::: "memory");
    };

    // prologue: stage first tile
    issue_prefetch(blockIdx.x * RPT);
    asm volatile("cp.async.wait_group 0;" ::: "memory");
    __syncthreads();

    for (int tile = blockIdx.x; tile < ntiles; tile += gridDim.x) {
        const int row0 = tile * RPT;
        const int nt   = tile + gridDim.x;

        // ---- P1: projection partials ----
        #pragma unroll 4
        for (int rf = 0; rf < NRF; rf++) {
            const ulonglong2* fp =
                reinterpret_cast<const ulonglong2*>(s->f + rf * IN_DIM);
            u64 a0 = 0ull, a1 = 0ull;
            #pragma unroll
            for (int c = 0; c < 8; c++) {
                ulonglong2 fv = fp[kg * 32 + 4 * c + ksub];
                ffma2(a0, wpp[2 * c],     fv.x);
                ffma2(a1, wpp[2 * c + 1], fv.y);
            }
            float p = hsum2(a0, a1);
            p += __shfl_xor_sync(FULL_MASK, p, 8);
            p += __shfl_xor_sync(FULL_MASK, p, 16);
            if (lane < 8)
                s->part[(rf * D + j) * 2 + kg] = p;
        }
        __syncthreads();                       // bar1: part ready, f free

        // ---- issue prefetch of next tile into f (async, waited at tile end) ----
        if (nt < ntiles) issue_prefetch(nt * RPT);

        // ---- P2: reduce + relu + LN (warp w: rf = w, w+8, w+16) ----
        #pragma unroll
        for (int idx = 0; idx < 3; idx++) {
            int rf = w + idx * 8;
            float2 pr = reinterpret_cast<const float2*>(s->part)[rf * D + lane];
            float h = fmaxf(bp_l + pr.x + pr.y, 0.f);
            float mu  = wsum(h) * (1.f / 32.f);
            float dv  = h - mu;
            float var = wsum(dv * dv) * (1.f / 32.f);
            s->x[rf * D + lane] = g_l * dv * rsqrtf(var + LN_EPS) + b_l;
        }
        __syncthreads();                       // bar2: x ready

        // ---- P3: per-row QKV + attention + O (warp w owns row w) ----
        const int row = row0 + w;
        if (row < B) {
            float qkvr[3][3];  // [mat][s]
            float bias3[3] = { bq_l, bk_l, bv_l };
            #pragma unroll
            for (int mat = 0; mat < 3; mat++) {
                const ulonglong2* wrow = reinterpret_cast<const ulonglong2*>(
                    s->w5 + mat * D * WSTRIDE + lane * WSTRIDE);
                u64 a0[3] = {0ull,0ull,0ull}, a1[3] = {0ull,0ull,0ull};
                #pragma unroll
                for (int c = 0; c < 8; c++) {
                    ulonglong2 wv = wrow[c];
                    #pragma unroll
                    for (int ss = 0; ss < 3; ss++) {
                        ulonglong2 xv = reinterpret_cast<const ulonglong2*>(
                            s->x + (w * 3 + ss) * D)[c];
                        ffma2(a0[ss], wv.x, xv.x);
                        ffma2(a1[ss], wv.y, xv.y);
                    }
                }
                #pragma unroll
                for (int ss = 0; ss < 3; ss++)
                    qkvr[mat][ss] = hsum2(a0[ss], a1[ss]) + bias3[mat];
            }

            const float scale = 0.17677669529663687f;   // 1/sqrt(32)
            float att[3][3];
            #pragma unroll
            for (int ss = 0; ss < 3; ss++)
                #pragma unroll
                for (int tt = 0; tt < 3; tt++)
                    att[ss][tt] = wsum(qkvr[0][ss] * qkvr[1][tt]) * scale;

            float pooled = 0.f;
            #pragma unroll
            for (int ss = 0; ss < 3; ss++) {
                float m  = fmaxf(att[ss][0], fmaxf(att[ss][1], att[ss][2]));
                float e0 = __expf(att[ss][0] - m);
                float e1 = __expf(att[ss][1] - m);
                float e2 = __expf(att[ss][2] - m);
                float ri = 1.f / (e0 + e1 + e2);
                pooled += (e0 * qkvr[2][0] + e1 * qkvr[2][1] + e2 * qkvr[2][2]) * ri;
            }
            pooled *= (1.f / 3.f);
            s->pooled[w][lane] = pooled;
            __syncwarp();

            // O1 = relu(pooled @ Wo1^T + bo1)
            {
                const ulonglong2* pv = reinterpret_cast<const ulonglong2*>(s->pooled[w]);
                const ulonglong2* w1 = reinterpret_cast<const ulonglong2*>(
                    s->w5 + 3 * D * WSTRIDE + lane * WSTRIDE);
                u64 a0 = 0ull, a1 = 0ull;
                #pragma unroll
                for (int c = 0; c < 8; c++) {
                    ulonglong2 pvv = pv[c];
                    ulonglong2 wv  = w1[c];
                    ffma2(a0, wv.x, pvv.x);
                    ffma2(a1, wv.y, pvv.y);
                }
                s->o1[w][lane] = fmaxf(hsum2(a0, a1) + bo1_l, 0.f);
            }
            __syncwarp();

            // out = O1 @ Wo2^T + bo2 + pooled
            {
                const ulonglong2* ov = reinterpret_cast<const ulonglong2*>(s->o1[w]);
                const ulonglong2* w2 = reinterpret_cast<const ulonglong2*>(
                    s->w5 + 4 * D * WSTRIDE + lane * WSTRIDE);
                u64 a0 = 0ull, a1 = 0ull;
                #pragma unroll
                for (int c = 0; c < 8; c++) {
                    ulonglong2 ovv = ov[c];
                    ulonglong2 wv  = w2[c];
                    ffma2(a0, wv.x, ovv.x);
                    ffma2(a1, wv.y, ovv.y);
                }
                out[(size_t)row * D + lane] = hsum2(a0, a1) + bo2_l + pooled;
            }
        }

        // ---- close the tile: next f must have landed ----
        asm volatile("cp.async.wait_group 0;" ::: "memory");
        __syncthreads();                       // bar3
    }
}

extern "C" void kernel_launch(void* const* d_in, const int* in_sizes, int n_in,
                              void* d_out, int out_size)
{
    const float* f1   = (const float*)d_in[0];
    const float* f4   = (const float*)d_in[1];
    const float* fD   = (const float*)d_in[2];
    const float* Wp   = (const float*)d_in[3];
    const float* bp   = (const float*)d_in[4];
    const float* ln_g = (const float*)d_in[5];
    const float* ln_b = (const float*)d_in[6];
    const float* Wq   = (const float*)d_in[7];
    const float* bq   = (const float*)d_in[8];
    const float* Wk   = (const float*)d_in[9];
    const float* bk   = (const float*)d_in[10];
    const float* Wv   = (const float*)d_in[11];
    const float* bv   = (const float*)d_in[12];
    const float* Wo1  = (const float*)d_in[13];
    const float* bo1  = (const float*)d_in[14];
    const float* Wo2  = (const float*)d_in[15];
    const float* bo2  = (const float*)d_in[16];

    const int B = in_sizes[0] / IN_DIM;
    const int ntiles = (B + RPT - 1) / RPT;
    const int smem_bytes = (int)sizeof(Smem);

    cudaFuncSetAttribute(msfe_kernel, cudaFuncAttributeMaxDynamicSharedMemorySize, smem_bytes);

    int grid = ntiles < 456 ? ntiles : 456;   // 3 blocks x 152 SMs, persistent
    msfe_kernel<<<grid, THREADS, smem_bytes>>>(
        f1, f4, fD, Wp, bp, ln_g, ln_b, Wq, bq, Wk, bk, Wv, bv,
        Wo1, bo1, Wo2, bo2, (float*)d_out, B, ntiles);
}